// round 16
// baseline (speedup 1.0000x reference)
#include <cuda_runtime.h>
#include <cuda_fp16.h>
#include <cstdint>
#include <math.h>

// Problem constants
#define VV 27
#define EE 64
#define HH 128
#define BB 256
#define SE 512
#define SD 512

typedef unsigned long long ull;
typedef unsigned int u32;

// Scratch for decoder hidden states, fp16: [B, S_DEC, H] = 32 MB.
__device__ __half g_dec_h[(size_t)BB * SD * HH];

// ---- packed fp32x2 helpers (sm_103a FFMA2 / FADD2) ----
__device__ __forceinline__ void ffma2(ull& d, ull a, ull b) {
    asm("fma.rn.f32x2 %0, %1, %2, %0;" : "+l"(d) : "l"(a), "l"(b));
}
__device__ __forceinline__ ull addp2(ull a, ull b) {
    ull r; asm("add.rn.f32x2 %0, %1, %2;" : "=l"(r) : "l"(a), "l"(b)); return r;
}
__device__ __forceinline__ ull pack2(float x, float y) {
    ull r; asm("mov.b64 %0, {%1, %2};" : "=l"(r) : "f"(x), "f"(y)); return r;
}
__device__ __forceinline__ float2 unpack2(ull v) {
    float2 r; asm("mov.b64 {%0, %1}, %2;" : "=f"(r.x), "=f"(r.y) : "l"(v)); return r;
}

// Fast-but-accurate tanh: 1 - 2/(exp(2x)+1). abs err ~1e-6.
__device__ __forceinline__ float fast_tanh(float x) {
    float e = __expf(x * 2.0f);
    return 1.0f - __fdividef(2.0f, e + 1.0f);
}

// =====================================================================
// Kernel 1: fused encoder+decoder scan, split-dot ring.
// 128 CTAs x 256 threads; grp = tid>>7 = row, j = tid&127 = unit.
// Dot split into two INDEPENDENT accumulator sets: A (a0..a3, K[0:64])
// and B (b0..b3, K[64:128]). The cross-group arrive sits between them
// with explicit register dependences both ways:
//   - reads a0..a3  -> arrive cannot issue before block A finishes
//   - passes b0 through "+l" -> block B cannot issue before the arrive
// No memory clobber on the arrive and no load operands -> the 32
// LDS.128 stay free to front-batch (excludes the R11 failure) and no
// scoreboard wait enters the ring (excludes the R14 failure).
// Ring latency: release -> arrive is now loads + HALF the dot issue:
//   P = 2*(~165 + 47) ~ 430 vs 570 when the arrive trailed the full dot.
// =====================================================================
__global__ void __launch_bounds__(256, 1) scan_kernel(
    const int*   __restrict__ enc_ids, const int* __restrict__ dec_ids,
    const float* __restrict__ embed,
    const float* __restrict__ enc_Wx, const float* __restrict__ enc_Wh,
    const float* __restrict__ enc_b,
    const float* __restrict__ dec_Wx, const float* __restrict__ dec_Wh,
    const float* __restrict__ dec_b)
{
    __shared__ float tabE[VV][HH];
    __shared__ float tabD[VV][HH];
    __shared__ float emb_s[VV * EE];
    __shared__ __align__(16) float hbuf[2][2][HH];
    __shared__ int   idsE[2][SE];
    __shared__ int   idsD[2][SD];

    const int tid  = threadIdx.x;
    const int grp  = tid >> 7;
    const int j    = tid & (HH - 1);
    const int row0 = blockIdx.x * 2;
    const int row  = row0 + grp;

    for (int i = tid; i < VV * EE; i += 256) emb_s[i] = embed[i];
    for (int i = tid; i < SE; i += 256) {
        idsE[0][i] = enc_ids[(size_t)row0 * SE + i];
        idsE[1][i] = enc_ids[(size_t)(row0 + 1) * SE + i];
    }
    for (int i = tid; i < SD; i += 256) {
        idsD[0][i] = dec_ids[(size_t)row0 * SD + i];
        idsD[1][i] = dec_ids[(size_t)(row0 + 1) * SD + i];
    }
    __syncthreads();

    for (int idx = tid; idx < VV * HH; idx += 256) {
        const int v = idx / HH;
        const int h = idx - v * HH;
        float sE = enc_b[h];
        float sD = dec_b[h];
        #pragma unroll 8
        for (int e = 0; e < EE; e++) {
            const float em = emb_s[v * EE + e];
            sE = fmaf(em, enc_Wx[e * HH + h], sE);
            sD = fmaf(em, dec_Wx[e * HH + h], sD);
        }
        tabE[v][h] = sE;
        tabD[v][h] = sD;
    }

    if (grp == 0) { hbuf[0][0][j] = 0.0f; hbuf[0][1][j] = 0.0f; }
    __syncthreads();

    ull w2[HH / 2];
    #pragma unroll
    for (int k = 0; k < HH / 2; k++)
        w2[k] = pack2(enc_Wh[(2 * k) * HH + j], enc_Wh[(2 * k + 1) * HH + j]);

    // prime the ring
    if (grp == 1)
        asm volatile("bar.arrive 4, 256;" ::: "memory");

    // ---- encoder phase ----
    int cur = 0;
    float tb = tabE[idsE[grp][0]][j];
    for (int t = 0; t < SE; t++) {
        if (grp == 0) asm volatile("bar.sync 4, 256;" ::: "memory");
        else          asm volatile("bar.sync 3, 256;" ::: "memory");

        const ulonglong2* hq = (const ulonglong2*)hbuf[cur][grp];

        // block A: K[0:64] -> a0..a3 (32 FFMA2)
        ull a0 = pack2(tb, 0.0f), a1 = 0, a2 = 0, a3 = 0;
        #pragma unroll
        for (int q = 0; q < 16; q += 2) {
            ulonglong2 h0 = hq[q];
            ulonglong2 h1 = hq[q + 1];
            ffma2(a0, h0.x, w2[2 * q + 0]);
            ffma2(a1, h0.y, w2[2 * q + 1]);
            ffma2(a2, h1.x, w2[2 * q + 2]);
            ffma2(a3, h1.y, w2[2 * q + 3]);
        }
        // mid-dot arrive: after A (reads a0..a3), before B (b0 threads
        // through). bar.arrive writes nothing, so b0 stays 0.
        ull b0 = 0, b1 = 0, b2 = 0, b3 = 0;
        if (grp == 0)
            asm volatile("bar.arrive 3, 256;"
                         : "+l"(b0)
                         : "l"(a0), "l"(a1), "l"(a2), "l"(a3));
        else
            asm volatile("bar.arrive 4, 256;"
                         : "+l"(b0)
                         : "l"(a0), "l"(a1), "l"(a2), "l"(a3));
        // block B: K[64:128] -> b0..b3 (32 FFMA2)
        #pragma unroll
        for (int q = 16; q < 32; q += 2) {
            ulonglong2 h0 = hq[q];
            ulonglong2 h1 = hq[q + 1];
            ffma2(b0, h0.x, w2[2 * q + 0]);
            ffma2(b1, h0.y, w2[2 * q + 1]);
            ffma2(b2, h1.x, w2[2 * q + 2]);
            ffma2(b3, h1.y, w2[2 * q + 3]);
        }

        const int tn = (t + 1 < SE) ? t + 1 : t;
        const float nb = tabE[idsE[grp][tn]][j];

        const ull mA = addp2(addp2(a0, a2), addp2(a1, a3));
        const ull mB = addp2(addp2(b0, b2), addp2(b1, b3));
        float2 s = unpack2(addp2(mA, mB));
        const float hn = fast_tanh(s.x + s.y);
        hbuf[cur ^ 1][grp][j] = hn;
        cur ^= 1;
        tb = nb;
    }

    // ---- decoder phase ----
    #pragma unroll
    for (int k = 0; k < HH / 2; k++)
        w2[k] = pack2(dec_Wh[(2 * k) * HH + j], dec_Wh[(2 * k + 1) * HH + j]);

    __half* outrow = g_dec_h + (size_t)row * SD * HH;
    tb = tabD[idsD[grp][0]][j];
    for (int t = 0; t < SD; t++) {
        if (grp == 0) asm volatile("bar.sync 4, 256;" ::: "memory");
        else          asm volatile("bar.sync 3, 256;" ::: "memory");

        const ulonglong2* hq = (const ulonglong2*)hbuf[cur][grp];

        ull a0 = pack2(tb, 0.0f), a1 = 0, a2 = 0, a3 = 0;
        #pragma unroll
        for (int q = 0; q < 16; q += 2) {
            ulonglong2 h0 = hq[q];
            ulonglong2 h1 = hq[q + 1];
            ffma2(a0, h0.x, w2[2 * q + 0]);
            ffma2(a1, h0.y, w2[2 * q + 1]);
            ffma2(a2, h1.x, w2[2 * q + 2]);
            ffma2(a3, h1.y, w2[2 * q + 3]);
        }
        ull b0 = 0, b1 = 0, b2 = 0, b3 = 0;
        if (grp == 0)
            asm volatile("bar.arrive 3, 256;"
                         : "+l"(b0)
                         : "l"(a0), "l"(a1), "l"(a2), "l"(a3));
        else
            asm volatile("bar.arrive 4, 256;"
                         : "+l"(b0)
                         : "l"(a0), "l"(a1), "l"(a2), "l"(a3));
        #pragma unroll
        for (int q = 16; q < 32; q += 2) {
            ulonglong2 h0 = hq[q];
            ulonglong2 h1 = hq[q + 1];
            ffma2(b0, h0.x, w2[2 * q + 0]);
            ffma2(b1, h0.y, w2[2 * q + 1]);
            ffma2(b2, h1.x, w2[2 * q + 2]);
            ffma2(b3, h1.y, w2[2 * q + 3]);
        }

        const int tn = (t + 1 < SD) ? t + 1 : t;
        const float nb = tabD[idsD[grp][tn]][j];

        const ull mA = addp2(addp2(a0, a2), addp2(a1, a3));
        const ull mB = addp2(addp2(b0, b2), addp2(b1, b3));
        float2 s = unpack2(addp2(mA, mB));
        const float hn = fast_tanh(s.x + s.y);
        hbuf[cur ^ 1][grp][j] = hn;
        outrow[t * HH + j] = __float2half_rn(hn);   // off-chain store
        cur ^= 1;
        tb = nb;
    }
}

// =====================================================================
// Kernel 2: logits via tensor cores (R15 best: 64-token tiles, 2048
// CTAs x 128 threads, vectorized W staging, coalesced epilogue).
// =====================================================================
__global__ void __launch_bounds__(128) logits_kernel(
    const float* __restrict__ dense_W, const float* __restrict__ dense_b,
    float* __restrict__ out)
{
    __shared__ __align__(16) __half hs[64 * 136];    // 17 KB h tile
    __shared__ __align__(16) __half w_s[32 * 136];   // 8.5 KB W^T
    __shared__ __align__(16) float  Ls[64 * VV];     // 6.9 KB logit tile
    __shared__ float bias_s[32];

    const int tid  = threadIdx.x;
    const int lane = tid & 31;
    const int wid  = tid >> 5;            // 0..3
    const size_t tok0 = (size_t)blockIdx.x * 64;

    // stage h tile: 1024 uint4, 8 per thread
    const uint4* src = (const uint4*)(g_dec_h + tok0 * HH);
    #pragma unroll
    for (int i = 0; i < 8; i++) {
        const int idx = tid + 128 * i;
        const int row = idx >> 4, part = idx & 15;
        *(uint4*)&hs[row * 136 + part * 8] = src[idx];
    }

    // zero ONLY pad rows v in [27,32): 5*136 halfs = 85 uint4
    if (tid < 85)
        ((uint4*)(w_s + 27 * 136))[tid] = make_uint4(0, 0, 0, 0);

    // vectorized W fill: dense_W = [128][27] f32 row-major = 864 float4
    for (int i = tid; i < 864; i += 128) {
        const float4 wv = ((const float4*)dense_W)[i];
        int f = i * 4;
        int k = f / 27;
        int v = f - k * 27;
        w_s[v * 136 + k] = __float2half_rn(wv.x);
        if (++v == VV) { v = 0; k++; }
        w_s[v * 136 + k] = __float2half_rn(wv.y);
        if (++v == VV) { v = 0; k++; }
        w_s[v * 136 + k] = __float2half_rn(wv.z);
        if (++v == VV) { v = 0; k++; }
        w_s[v * 136 + k] = __float2half_rn(wv.w);
    }
    if (tid < 32) bias_s[tid] = (tid < VV) ? dense_b[tid] : 0.0f;
    __syncthreads();

    const int gi = lane >> 2;
    const int ci = lane & 3;
    const int m0 = wid * 16;

    float c[4][4] = {};
    #pragma unroll
    for (int ks = 0; ks < 8; ks++) {
        const int k = ks * 16 + ci * 2;
        const u32 a0 = *(const u32*)&hs[(m0 + gi)     * 136 + k];
        const u32 a1 = *(const u32*)&hs[(m0 + gi + 8) * 136 + k];
        const u32 a2 = *(const u32*)&hs[(m0 + gi)     * 136 + k + 8];
        const u32 a3 = *(const u32*)&hs[(m0 + gi + 8) * 136 + k + 8];
        #pragma unroll
        for (int nt = 0; nt < 4; nt++) {
            const int cc = nt * 8 + gi;
            const u32 b0 = *(const u32*)&w_s[cc * 136 + k];
            const u32 b1 = *(const u32*)&w_s[cc * 136 + k + 8];
            asm volatile(
                "mma.sync.aligned.m16n8k16.row.col.f32.f16.f16.f32 "
                "{%0,%1,%2,%3}, {%4,%5,%6,%7}, {%8,%9}, {%0,%1,%2,%3};"
                : "+f"(c[nt][0]), "+f"(c[nt][1]), "+f"(c[nt][2]), "+f"(c[nt][3])
                : "r"(a0), "r"(a1), "r"(a2), "r"(a3), "r"(b0), "r"(b1));
        }
    }

    #pragma unroll
    for (int nt = 0; nt < 4; nt++) {
        const int col = nt * 8 + ci * 2;
        const int r0 = m0 + gi;
        if (col < VV) {
            Ls[r0 * VV + col]       = c[nt][0] + bias_s[col];
            Ls[(r0 + 8) * VV + col] = c[nt][2] + bias_s[col];
        }
        if (col + 1 < VV) {
            Ls[r0 * VV + col + 1]       = c[nt][1] + bias_s[col + 1];
            Ls[(r0 + 8) * VV + col + 1] = c[nt][3] + bias_s[col + 1];
        }
    }
    __syncthreads();

    float4* dst = (float4*)(out + tok0 * VV);
    const float4* srcL = (const float4*)Ls;
    #pragma unroll
    for (int i = 0; i < 4; i++) {
        const int idx = tid + 128 * i;
        if (idx < (64 * VV) / 4) dst[idx] = srcL[idx];
    }
}

// =====================================================================
extern "C" void kernel_launch(void* const* d_in, const int* in_sizes, int n_in,
                              void* d_out, int out_size) {
    const int*   enc_ids = (const int*)  d_in[0];
    const int*   dec_ids = (const int*)  d_in[1];
    const float* embed   = (const float*)d_in[2];
    const float* enc_Wx  = (const float*)d_in[3];
    const float* enc_Wh  = (const float*)d_in[4];
    const float* enc_b   = (const float*)d_in[5];
    const float* dec_Wx  = (const float*)d_in[6];
    const float* dec_Wh  = (const float*)d_in[7];
    const float* dec_b   = (const float*)d_in[8];
    const float* dense_W = (const float*)d_in[9];
    const float* dense_b = (const float*)d_in[10];
    float* out = (float*)d_out;

    scan_kernel<<<BB / 2, 256>>>(enc_ids, dec_ids, embed,
                                 enc_Wx, enc_Wh, enc_b,
                                 dec_Wx, dec_Wh, dec_b);
    logits_kernel<<<(BB * SD) / 64, 128>>>(dense_W, dense_b, out);
}

// round 17
// speedup vs baseline: 1.1377x; 1.1377x over previous
#include <cuda_runtime.h>
#include <cuda_fp16.h>
#include <cstdint>
#include <math.h>

// Problem constants
#define VV 27
#define EE 64
#define HH 128
#define BB 256
#define SE 512
#define SD 512

typedef unsigned long long ull;
typedef unsigned int u32;

// Scratch for decoder hidden states, fp16: [B, S_DEC, H] = 32 MB.
__device__ __half g_dec_h[(size_t)BB * SD * HH];

// ---- packed fp32x2 helpers (sm_103a FFMA2 / FADD2) ----
__device__ __forceinline__ void ffma2(ull& d, ull a, ull b) {
    asm("fma.rn.f32x2 %0, %1, %2, %0;" : "+l"(d) : "l"(a), "l"(b));
}
__device__ __forceinline__ ull addp2(ull a, ull b) {
    ull r; asm("add.rn.f32x2 %0, %1, %2;" : "=l"(r) : "l"(a), "l"(b)); return r;
}
__device__ __forceinline__ ull pack2(float x, float y) {
    ull r; asm("mov.b64 %0, {%1, %2};" : "=l"(r) : "f"(x), "f"(y)); return r;
}
__device__ __forceinline__ float2 unpack2(ull v) {
    float2 r; asm("mov.b64 {%0, %1}, %2;" : "=f"(r.x), "=f"(r.y) : "l"(v)); return r;
}

// Fast-but-accurate tanh: 1 - 2/(exp(2x)+1). abs err ~1e-6.
__device__ __forceinline__ float fast_tanh(float x) {
    float e = __expf(x * 2.0f);
    return 1.0f - __fdividef(2.0f, e + 1.0f);
}

__device__ __forceinline__ u32 smem_u32(const void* p) {
    return (u32)__cvta_generic_to_shared(p);
}
__device__ __forceinline__ void ldsm_x4(u32& r0, u32& r1, u32& r2, u32& r3,
                                        u32 addr) {
    asm volatile("ldmatrix.sync.aligned.m8n8.x4.shared.b16 "
                 "{%0,%1,%2,%3}, [%4];"
                 : "=r"(r0), "=r"(r1), "=r"(r2), "=r"(r3) : "r"(addr));
}

// =====================================================================
// Kernel 1: fused encoder+decoder scan (R12, measured best ~327us;
// three mid-dot-release variants all regressed — arrive trails the
// full dot). 128 CTAs x 256 threads; grp = tid>>7, j = tid&127.
// =====================================================================
__global__ void __launch_bounds__(256, 1) scan_kernel(
    const int*   __restrict__ enc_ids, const int* __restrict__ dec_ids,
    const float* __restrict__ embed,
    const float* __restrict__ enc_Wx, const float* __restrict__ enc_Wh,
    const float* __restrict__ enc_b,
    const float* __restrict__ dec_Wx, const float* __restrict__ dec_Wh,
    const float* __restrict__ dec_b)
{
    __shared__ float tabE[VV][HH];
    __shared__ float tabD[VV][HH];
    __shared__ float emb_s[VV * EE];
    __shared__ __align__(16) float hbuf[2][2][HH];
    __shared__ int   idsE[2][SE];
    __shared__ int   idsD[2][SD];

    const int tid  = threadIdx.x;
    const int grp  = tid >> 7;
    const int j    = tid & (HH - 1);
    const int row0 = blockIdx.x * 2;
    const int row  = row0 + grp;

    for (int i = tid; i < VV * EE; i += 256) emb_s[i] = embed[i];
    for (int i = tid; i < SE; i += 256) {
        idsE[0][i] = enc_ids[(size_t)row0 * SE + i];
        idsE[1][i] = enc_ids[(size_t)(row0 + 1) * SE + i];
    }
    for (int i = tid; i < SD; i += 256) {
        idsD[0][i] = dec_ids[(size_t)row0 * SD + i];
        idsD[1][i] = dec_ids[(size_t)(row0 + 1) * SD + i];
    }
    __syncthreads();

    for (int idx = tid; idx < VV * HH; idx += 256) {
        const int v = idx / HH;
        const int h = idx - v * HH;
        float sE = enc_b[h];
        float sD = dec_b[h];
        #pragma unroll 8
        for (int e = 0; e < EE; e++) {
            const float em = emb_s[v * EE + e];
            sE = fmaf(em, enc_Wx[e * HH + h], sE);
            sD = fmaf(em, dec_Wx[e * HH + h], sD);
        }
        tabE[v][h] = sE;
        tabD[v][h] = sD;
    }

    if (grp == 0) { hbuf[0][0][j] = 0.0f; hbuf[0][1][j] = 0.0f; }
    __syncthreads();

    ull w2[HH / 2];
    #pragma unroll
    for (int k = 0; k < HH / 2; k++)
        w2[k] = pack2(enc_Wh[(2 * k) * HH + j], enc_Wh[(2 * k + 1) * HH + j]);

    // prime the ring
    if (grp == 1)
        asm volatile("bar.arrive 4, 256;" ::: "memory");

    // ---- encoder phase ----
    int cur = 0;
    float tb = tabE[idsE[grp][0]][j];
    for (int t = 0; t < SE; t++) {
        if (grp == 0) asm volatile("bar.sync 4, 256;" ::: "memory");
        else          asm volatile("bar.sync 3, 256;" ::: "memory");

        const ulonglong2* hq = (const ulonglong2*)hbuf[cur][grp];
        ull a0 = pack2(tb, 0.0f), a1 = 0, a2 = 0, a3 = 0;
        #pragma unroll
        for (int q = 0; q < HH / 4; q += 2) {
            ulonglong2 h0 = hq[q];
            ulonglong2 h1 = hq[q + 1];
            ffma2(a0, h0.x, w2[2 * q + 0]);
            ffma2(a1, h0.y, w2[2 * q + 1]);
            ffma2(a2, h1.x, w2[2 * q + 2]);
            ffma2(a3, h1.y, w2[2 * q + 3]);
        }
        if (grp == 0) asm volatile("bar.arrive 3, 256;"
                                   :: "l"(a0), "l"(a1), "l"(a2), "l"(a3));
        else          asm volatile("bar.arrive 4, 256;"
                                   :: "l"(a0), "l"(a1), "l"(a2), "l"(a3));

        const int tn = (t + 1 < SE) ? t + 1 : t;
        const float nb = tabE[idsE[grp][tn]][j];

        float2 s = unpack2(addp2(addp2(a0, a2), addp2(a1, a3)));
        const float hn = fast_tanh(s.x + s.y);
        hbuf[cur ^ 1][grp][j] = hn;
        cur ^= 1;
        tb = nb;
    }

    // ---- decoder phase ----
    #pragma unroll
    for (int k = 0; k < HH / 2; k++)
        w2[k] = pack2(dec_Wh[(2 * k) * HH + j], dec_Wh[(2 * k + 1) * HH + j]);

    __half* outrow = g_dec_h + (size_t)row * SD * HH;
    tb = tabD[idsD[grp][0]][j];
    for (int t = 0; t < SD; t++) {
        if (grp == 0) asm volatile("bar.sync 4, 256;" ::: "memory");
        else          asm volatile("bar.sync 3, 256;" ::: "memory");

        const ulonglong2* hq = (const ulonglong2*)hbuf[cur][grp];
        ull a0 = pack2(tb, 0.0f), a1 = 0, a2 = 0, a3 = 0;
        #pragma unroll
        for (int q = 0; q < HH / 4; q += 2) {
            ulonglong2 h0 = hq[q];
            ulonglong2 h1 = hq[q + 1];
            ffma2(a0, h0.x, w2[2 * q + 0]);
            ffma2(a1, h0.y, w2[2 * q + 1]);
            ffma2(a2, h1.x, w2[2 * q + 2]);
            ffma2(a3, h1.y, w2[2 * q + 3]);
        }
        if (grp == 0) asm volatile("bar.arrive 3, 256;"
                                   :: "l"(a0), "l"(a1), "l"(a2), "l"(a3));
        else          asm volatile("bar.arrive 4, 256;"
                                   :: "l"(a0), "l"(a1), "l"(a2), "l"(a3));

        const int tn = (t + 1 < SD) ? t + 1 : t;
        const float nb = tabD[idsD[grp][tn]][j];

        float2 s = unpack2(addp2(addp2(a0, a2), addp2(a1, a3)));
        const float hn = fast_tanh(s.x + s.y);
        hbuf[cur ^ 1][grp][j] = hn;
        outrow[t * HH + j] = __float2half_rn(hn);   // off-chain store
        cur ^= 1;
        tb = nb;
    }
}

// =====================================================================
// Kernel 2: logits via tensor cores, LDSM fragment loads.
// 64-token tiles, 2048 CTAs x 128 threads. Per ks: 1 ldmatrix.x4 for
// the A fragment (row = m0+(lane&15), k-half = lane>>4) and 2
// ldmatrix.x4 for all 4 B n-tiles (row = lane = n index), replacing
// 12 scalar LDS.32 per thread per ks. 272B row stride => each 8x8
// matrix's rows land at 16B-offset banks covering 128B: conflict-free.
// =====================================================================
__global__ void __launch_bounds__(128) logits_kernel(
    const float* __restrict__ dense_W, const float* __restrict__ dense_b,
    float* __restrict__ out)
{
    __shared__ __align__(16) __half hs[64 * 136];    // 17 KB h tile
    __shared__ __align__(16) __half w_s[32 * 136];   // 8.5 KB W^T
    __shared__ __align__(16) float  Ls[64 * VV];     // 6.9 KB logit tile
    __shared__ float bias_s[32];

    const int tid  = threadIdx.x;
    const int lane = tid & 31;
    const int wid  = tid >> 5;            // 0..3
    const size_t tok0 = (size_t)blockIdx.x * 64;

    // stage h tile: 1024 uint4, 8 per thread
    const uint4* src = (const uint4*)(g_dec_h + tok0 * HH);
    #pragma unroll
    for (int i = 0; i < 8; i++) {
        const int idx = tid + 128 * i;
        const int row = idx >> 4, part = idx & 15;
        *(uint4*)&hs[row * 136 + part * 8] = src[idx];
    }

    // zero ONLY pad rows v in [27,32): 5*136 halfs = 85 uint4
    if (tid < 85)
        ((uint4*)(w_s + 27 * 136))[tid] = make_uint4(0, 0, 0, 0);

    // vectorized W fill: dense_W = [128][27] f32 row-major = 864 float4
    for (int i = tid; i < 864; i += 128) {
        const float4 wv = ((const float4*)dense_W)[i];
        int f = i * 4;
        int k = f / 27;
        int v = f - k * 27;
        w_s[v * 136 + k] = __float2half_rn(wv.x);
        if (++v == VV) { v = 0; k++; }
        w_s[v * 136 + k] = __float2half_rn(wv.y);
        if (++v == VV) { v = 0; k++; }
        w_s[v * 136 + k] = __float2half_rn(wv.z);
        if (++v == VV) { v = 0; k++; }
        w_s[v * 136 + k] = __float2half_rn(wv.w);
    }
    if (tid < 32) bias_s[tid] = (tid < VV) ? dense_b[tid] : 0.0f;
    __syncthreads();

    const int gi = lane >> 2;
    const int ci = lane & 3;
    const int m0 = wid * 16;

    // ldmatrix base addresses (byte stride per row = 136*2 = 272)
    const u32 a_base = smem_u32(hs) + (u32)(m0 + (lane & 15)) * 272u
                                    + (u32)(lane >> 4) * 16u;
    const u32 b_base = smem_u32(w_s) + (u32)lane * 272u;

    float c[4][4] = {};
    #pragma unroll
    for (int ks = 0; ks < 8; ks++) {
        const u32 koff = (u32)ks * 32u;          // 16 halfs = 32 bytes
        u32 a0, a1, a2, a3;
        ldsm_x4(a0, a1, a2, a3, a_base + koff);  // A frag, all 4 regs
        u32 b0n0, b0n1, b0n2, b0n3;              // b0 for nt = 0..3
        ldsm_x4(b0n0, b0n1, b0n2, b0n3, b_base + koff);
        u32 b1n0, b1n1, b1n2, b1n3;              // b1 for nt = 0..3
        ldsm_x4(b1n0, b1n1, b1n2, b1n3, b_base + koff + 16u);

        asm volatile(
            "mma.sync.aligned.m16n8k16.row.col.f32.f16.f16.f32 "
            "{%0,%1,%2,%3}, {%4,%5,%6,%7}, {%8,%9}, {%0,%1,%2,%3};"
            : "+f"(c[0][0]), "+f"(c[0][1]), "+f"(c[0][2]), "+f"(c[0][3])
            : "r"(a0), "r"(a1), "r"(a2), "r"(a3), "r"(b0n0), "r"(b1n0));
        asm volatile(
            "mma.sync.aligned.m16n8k16.row.col.f32.f16.f16.f32 "
            "{%0,%1,%2,%3}, {%4,%5,%6,%7}, {%8,%9}, {%0,%1,%2,%3};"
            : "+f"(c[1][0]), "+f"(c[1][1]), "+f"(c[1][2]), "+f"(c[1][3])
            : "r"(a0), "r"(a1), "r"(a2), "r"(a3), "r"(b0n1), "r"(b1n1));
        asm volatile(
            "mma.sync.aligned.m16n8k16.row.col.f32.f16.f16.f32 "
            "{%0,%1,%2,%3}, {%4,%5,%6,%7}, {%8,%9}, {%0,%1,%2,%3};"
            : "+f"(c[2][0]), "+f"(c[2][1]), "+f"(c[2][2]), "+f"(c[2][3])
            : "r"(a0), "r"(a1), "r"(a2), "r"(a3), "r"(b0n2), "r"(b1n2));
        asm volatile(
            "mma.sync.aligned.m16n8k16.row.col.f32.f16.f16.f32 "
            "{%0,%1,%2,%3}, {%4,%5,%6,%7}, {%8,%9}, {%0,%1,%2,%3};"
            : "+f"(c[3][0]), "+f"(c[3][1]), "+f"(c[3][2]), "+f"(c[3][3])
            : "r"(a0), "r"(a1), "r"(a2), "r"(a3), "r"(b0n3), "r"(b1n3));
    }

    #pragma unroll
    for (int nt = 0; nt < 4; nt++) {
        const int col = nt * 8 + ci * 2;
        const int r0 = m0 + gi;
        if (col < VV) {
            Ls[r0 * VV + col]       = c[nt][0] + bias_s[col];
            Ls[(r0 + 8) * VV + col] = c[nt][2] + bias_s[col];
        }
        if (col + 1 < VV) {
            Ls[r0 * VV + col + 1]       = c[nt][1] + bias_s[col + 1];
            Ls[(r0 + 8) * VV + col + 1] = c[nt][3] + bias_s[col + 1];
        }
    }
    __syncthreads();

    float4* dst = (float4*)(out + tok0 * VV);
    const float4* srcL = (const float4*)Ls;
    #pragma unroll
    for (int i = 0; i < 4; i++) {
        const int idx = tid + 128 * i;
        if (idx < (64 * VV) / 4) dst[idx] = srcL[idx];
    }
}

// =====================================================================
extern "C" void kernel_launch(void* const* d_in, const int* in_sizes, int n_in,
                              void* d_out, int out_size) {
    const int*   enc_ids = (const int*)  d_in[0];
    const int*   dec_ids = (const int*)  d_in[1];
    const float* embed   = (const float*)d_in[2];
    const float* enc_Wx  = (const float*)d_in[3];
    const float* enc_Wh  = (const float*)d_in[4];
    const float* enc_b   = (const float*)d_in[5];
    const float* dec_Wx  = (const float*)d_in[6];
    const float* dec_Wh  = (const float*)d_in[7];
    const float* dec_b   = (const float*)d_in[8];
    const float* dense_W = (const float*)d_in[9];
    const float* dense_b = (const float*)d_in[10];
    float* out = (float*)d_out;

    scan_kernel<<<BB / 2, 256>>>(enc_ids, dec_ids, embed,
                                 enc_Wx, enc_Wh, enc_b,
                                 dec_Wx, dec_Wh, dec_b);
    logits_kernel<<<(BB * SD) / 64, 128>>>(dense_W, dense_b, out);
}